// round 15
// baseline (speedup 1.0000x reference)
#include <cuda_runtime.h>
#include <cuda_bf16.h>
#include <math.h>
#include <stdint.h>

// Problem constants
#define N_NODES   10000
#define N_EDGES   160000
#define IN_DIM    128
#define HID       16
#define HEADS     50
#define HC        800           // HEADS*HID
#define OUT_DIM   10
#define N_GRAPHS  8
#define NEG_SLOPE 0.2f
#define MAXDEG    96

// Scratch (device globals; zero-initialized at load)
__device__ float g_xpf[N_NODES * HC];   // 32 MB fp32 projected features (L2-resident)
__device__ float g_as[N_NODES * HEADS];
__device__ float g_ad[N_NODES * HEADS];
__device__ float g_gsum[N_GRAPHS * HID];
__device__ float g_gcnt[N_GRAPHS];
__device__ int   g_done;                // last-block ticket (zero-invariant)
// direct-slot adjacency (by destination)
__device__ int g_csr_cnt[N_NODES];      // invariant: zero at start of every run
__device__ int g_slots[N_NODES * MAXDEG];

// ---------------- tf32 GEMM (+ fused adjacency fill blocks) ---------------
#define GBM 128
#define GBN 64
#define GBK 32
#define ASTR 36
#define BSTR 68
#define NKT  (IN_DIM / GBK)
#define GEMM_BX ((HC + GBN - 1) / GBN)        // 13
#define GEMM_BY ((N_NODES + GBM - 1) / GBM)   // 79
#define GEMM_BLOCKS (GEMM_BX * GEMM_BY)       // 1027
#define FILL_BLOCKS ((N_EDGES + 255) / 256)   // 625

__device__ __forceinline__ void cp16(uint32_t dst, const float* src, int pred_bytes) {
    asm volatile("cp.async.ca.shared.global [%0], [%1], 16, %2;"
                 :: "r"(dst), "l"(src), "r"(pred_bytes));
}

__device__ __forceinline__ uint32_t f2tf32(float f) {
    uint32_t r;
    asm("cvt.rna.tf32.f32 %0, %1;" : "=r"(r) : "f"(f));
    return r;
}

__device__ __forceinline__ void mma_tf32(float c[4], const uint32_t a[4], const uint32_t b[2]) {
    asm volatile(
        "mma.sync.aligned.m16n8k8.row.col.f32.tf32.tf32.f32 "
        "{%0,%1,%2,%3}, {%4,%5,%6,%7}, {%8,%9}, {%0,%1,%2,%3};"
        : "+f"(c[0]), "+f"(c[1]), "+f"(c[2]), "+f"(c[3])
        : "r"(a[0]), "r"(a[1]), "r"(a[2]), "r"(a[3]), "r"(b[0]), "r"(b[1]));
}

__global__ void __launch_bounds__(256) k_fillgemm(const float* __restrict__ A,
                                                  const float* __restrict__ B,
                                                  const int* __restrict__ ei) {
    __shared__ float As[2][GBM][ASTR];
    __shared__ float Bs[2][GBK][BSTR];

    if (blockIdx.x >= GEMM_BLOCKS) {
        // adjacency fill (direct slots; no count/scan passes)
        int i = (blockIdx.x - GEMM_BLOCKS) * 256 + threadIdx.x;
        if (i < N_EDGES) {
            int dst = ei[N_EDGES + i];
            int k = atomicAdd(&g_csr_cnt[dst], 1);
            if (k < MAXDEG) g_slots[dst * MAXDEG + k] = ei[i];
        }
        return;
    }

    int tid = threadIdx.x;
    int lane = tid & 31;
    int warp = tid >> 5;
    int wm = warp >> 1;
    int wn = warp & 1;
    int grp = lane >> 2;
    int thr = lane & 3;
    int rowBase = (blockIdx.x / GEMM_BX) * GBM;
    int colBase = (blockIdx.x % GEMM_BX) * GBN;

    uint32_t sA0 = (uint32_t)__cvta_generic_to_shared(&As[0][0][0]);
    uint32_t sB0 = (uint32_t)__cvta_generic_to_shared(&Bs[0][0][0]);
    const uint32_t sAstage = GBM * ASTR * 4;
    const uint32_t sBstage = GBK * BSTR * 4;

    int ar[4], ac4[4], apred[4];
#pragma unroll
    for (int i = 0; i < 4; i++) {
        int idx = i * 256 + tid;
        ar[i] = idx >> 3;
        ac4[i] = idx & 7;
        apred[i] = (rowBase + ar[i] < N_NODES) ? 16 : 0;
    }
    int br[2], bc4[2], bpred[2];
#pragma unroll
    for (int i = 0; i < 2; i++) {
        int idx = i * 256 + tid;
        br[i] = idx >> 4;
        bc4[i] = idx & 15;
        bpred[i] = (colBase + bc4[i] * 4 < HC) ? 16 : 0;
    }

#pragma unroll
    for (int i = 0; i < 4; i++)
        cp16(sA0 + (ar[i] * ASTR + ac4[i] * 4) * 4,
             A + (size_t)(rowBase + ar[i]) * IN_DIM + ac4[i] * 4, apred[i]);
#pragma unroll
    for (int i = 0; i < 2; i++)
        cp16(sB0 + (br[i] * BSTR + bc4[i] * 4) * 4,
             B + (size_t)br[i] * HC + colBase + bc4[i] * 4, bpred[i]);
    asm volatile("cp.async.commit_group;");

    float c[2][4][4];
#pragma unroll
    for (int mt = 0; mt < 2; mt++)
#pragma unroll
        for (int nt = 0; nt < 4; nt++)
#pragma unroll
            for (int r = 0; r < 4; r++) c[mt][nt][r] = 0.0f;

#pragma unroll
    for (int kt = 0; kt < NKT; kt++) {
        int buf = kt & 1;
        if (kt + 1 < NKT) {
            int k0 = (kt + 1) * GBK;
            uint32_t dA = sA0 + (buf ^ 1) * sAstage;
            uint32_t dB = sB0 + (buf ^ 1) * sBstage;
#pragma unroll
            for (int i = 0; i < 4; i++)
                cp16(dA + (ar[i] * ASTR + ac4[i] * 4) * 4,
                     A + (size_t)(rowBase + ar[i]) * IN_DIM + k0 + ac4[i] * 4, apred[i]);
#pragma unroll
            for (int i = 0; i < 2; i++)
                cp16(dB + (br[i] * BSTR + bc4[i] * 4) * 4,
                     B + (size_t)(k0 + br[i]) * HC + colBase + bc4[i] * 4, bpred[i]);
            asm volatile("cp.async.commit_group;");
            asm volatile("cp.async.wait_group 1;");
        } else {
            asm volatile("cp.async.wait_group 0;");
        }
        __syncthreads();

        const float (*Ab)[ASTR] = As[buf];
        const float (*Bb)[BSTR] = Bs[buf];
#pragma unroll
        for (int kk = 0; kk < GBK; kk += 8) {
            uint32_t af[2][4], bf[4][2];
#pragma unroll
            for (int mt = 0; mt < 2; mt++) {
                int rb = wm * 32 + mt * 16;
                af[mt][0] = f2tf32(Ab[rb + grp][kk + thr]);
                af[mt][1] = f2tf32(Ab[rb + grp + 8][kk + thr]);
                af[mt][2] = f2tf32(Ab[rb + grp][kk + thr + 4]);
                af[mt][3] = f2tf32(Ab[rb + grp + 8][kk + thr + 4]);
            }
#pragma unroll
            for (int nt = 0; nt < 4; nt++) {
                int cb = wn * 32 + nt * 8;
                bf[nt][0] = f2tf32(Bb[kk + thr][cb + grp]);
                bf[nt][1] = f2tf32(Bb[kk + thr + 4][cb + grp]);
            }
#pragma unroll
            for (int mt = 0; mt < 2; mt++)
#pragma unroll
                for (int nt = 0; nt < 4; nt++)
                    mma_tf32(c[mt][nt], af[mt], bf[nt]);
        }
        __syncthreads();
    }

    // store fp32 xp (no conversion)
#pragma unroll
    for (int mt = 0; mt < 2; mt++) {
#pragma unroll
        for (int nt = 0; nt < 4; nt++) {
            int row0 = rowBase + wm * 32 + mt * 16 + grp;
            int col = colBase + wn * 32 + nt * 8 + thr * 2;
            if (col + 1 < HC) {
                if (row0 < N_NODES)
                    *(float2*)&g_xpf[(size_t)row0 * HC + col] =
                        make_float2(c[mt][nt][0], c[mt][nt][1]);
                if (row0 + 8 < N_NODES)
                    *(float2*)&g_xpf[(size_t)(row0 + 8) * HC + col] =
                        make_float2(c[mt][nt][2], c[mt][nt][3]);
            }
        }
    }
}

// ---------------- per-(node,head) attention dots from fp32 xp -------------
__global__ void __launch_bounds__(256) k_alphas(const float* __restrict__ a_src,
                                                const float* __restrict__ a_dst) {
    __shared__ float sas[HC];
    __shared__ float sad[HC];
    int t = threadIdx.x;
    for (int j = t; j < HC; j += 256) {
        sas[j] = a_src[j];
        sad[j] = a_dst[j];
    }
    __syncthreads();
    int i = blockIdx.x * 256 + t;
    if (i >= N_NODES * HEADS) return;
    int h = i % HEADS;
    const float4* xr = (const float4*)(g_xpf + (size_t)(i / HEADS) * HC + h * HID);
    float s = 0.0f, d = 0.0f;
    const float* as = sas + h * HID;
    const float* ad = sad + h * HID;
#pragma unroll
    for (int j = 0; j < 4; j++) {
        float4 v = xr[j];
        s += v.x * as[4 * j] + v.y * as[4 * j + 1] + v.z * as[4 * j + 2] + v.w * as[4 * j + 3];
        d += v.x * ad[4 * j] + v.y * ad[4 * j + 1] + v.z * ad[4 * j + 2] + v.w * ad[4 * j + 3];
    }
    g_as[i] = s;
    g_ad[i] = d;
}

// ---------------- fused softmax + aggregate + pool + FC (block per node) --
#define CAP 64
#define NCHUNK (HC / 8)      // 100 chunks of 8 floats (32 B)

__global__ void __launch_bounds__(256, 7) k_agg(const int* __restrict__ batch,
                                                const float* __restrict__ bias,
                                                const float* __restrict__ fc_w,
                                                const float* __restrict__ fc_b,
                                                float* __restrict__ out) {
    __shared__ float salpha[CAP * HEADS];   // 12.8 KB (raw exp weights)
    __shared__ float sout[HC];              // 3.2 KB
    __shared__ float sred[16][17];          // 1.1 KB epilogue tree
    __shared__ int      ssrc[CAP];          // src node ids (phase A)
    __shared__ uint32_t sbase[CAP];         // xpf byte offsets (phase B)
    __shared__ float sad[HEADS];
    __shared__ float sden[HEADS];
    __shared__ int slast;

    int i = blockIdx.x;
    int t = threadIdx.x;
    int w = t >> 5, lane = t & 31;
    int deg = g_csr_cnt[i];                 // read by EVERY thread (pre-reset)
    if (deg > MAXDEG) deg = MAXDEG;
    int d = deg + 1;                        // + self loop at index deg

    if (t < HEADS) {
        sad[t] = g_ad[i * HEADS + t];
        sden[t] = 0.0f;
    }

    if (d <= CAP) {
        // ---------------- fast path ----------------
        if (t < d) {
            int s = (t < deg) ? g_slots[i * MAXDEG + t] : i;
            ssrc[t] = s;
            sbase[t] = (uint32_t)s * (HC * 4);   // byte offset into g_xpf
        }
        __syncthreads();
        // reset AFTER the barrier: every thread's deg read is ordered before this store
        if (t == 0) g_csr_cnt[i] = 0;

        // phase A: warp per edge, lane = head; coalesced g_as row loads
        float ds0 = 0.0f, ds1 = 0.0f;
        for (int e = w; e < d; e += 8) {
            const float* asr = g_as + (size_t)ssrc[e] * HEADS;
            float v0 = asr[lane] + sad[lane];
            v0 = (v0 > 0.0f) ? v0 : NEG_SLOPE * v0;
            float ex0 = __expf(v0);
            salpha[e * HEADS + lane] = ex0;
            ds0 += ex0;
            if (lane < HEADS - 32) {
                float v1 = asr[32 + lane] + sad[32 + lane];
                v1 = (v1 > 0.0f) ? v1 : NEG_SLOPE * v1;
                float ex1 = __expf(v1);
                salpha[e * HEADS + 32 + lane] = ex1;
                ds1 += ex1;
            }
        }
        atomicAdd(&sden[lane], ds0);
        if (lane < HEADS - 32) atomicAdd(&sden[32 + lane], ds1);
        __syncthreads();
        if (t < HEADS) sden[t] = 1.0f / sden[t];

        // phase B: fp32 gather, 2-edge unroll (4 LDG.128 in flight), no unpack
        int slot = t >> 7;            // 0 or 1
        int cch = t & 127;            // chunk id, active if < NCHUNK
        float acc[8] = {0.f, 0.f, 0.f, 0.f, 0.f, 0.f, 0.f, 0.f};
        if (cch < NCHUNK) {
            int hsel = cch >> 1;
            const char* xb = (const char*)g_xpf;
            uint32_t coff = cch * 32;
            int e = slot;
            for (; e + 2 < d; e += 4) {
                float4 a0 = *(const float4*)(xb + sbase[e] + coff);
                float4 a1 = *(const float4*)(xb + sbase[e] + coff + 16);
                float4 b0 = *(const float4*)(xb + sbase[e + 2] + coff);
                float4 b1 = *(const float4*)(xb + sbase[e + 2] + coff + 16);
                float wa = salpha[e * HEADS + hsel];
                float wb = salpha[(e + 2) * HEADS + hsel];
                acc[0] += wa * a0.x; acc[1] += wa * a0.y;
                acc[2] += wa * a0.z; acc[3] += wa * a0.w;
                acc[4] += wa * a1.x; acc[5] += wa * a1.y;
                acc[6] += wa * a1.z; acc[7] += wa * a1.w;
                acc[0] += wb * b0.x; acc[1] += wb * b0.y;
                acc[2] += wb * b0.z; acc[3] += wb * b0.w;
                acc[4] += wb * b1.x; acc[5] += wb * b1.y;
                acc[6] += wb * b1.z; acc[7] += wb * b1.w;
            }
            for (; e < d; e += 2) {
                float4 a0 = *(const float4*)(xb + sbase[e] + coff);
                float4 a1 = *(const float4*)(xb + sbase[e] + coff + 16);
                float wa = salpha[e * HEADS + hsel];
                acc[0] += wa * a0.x; acc[1] += wa * a0.y;
                acc[2] += wa * a0.z; acc[3] += wa * a0.w;
                acc[4] += wa * a1.x; acc[5] += wa * a1.y;
                acc[6] += wa * a1.z; acc[7] += wa * a1.w;
            }
        }
        if (slot == 0 && cch < NCHUNK) {
#pragma unroll
            for (int jj = 0; jj < 8; jj++) sout[cch * 8 + jj] = acc[jj];
        }
        __syncthreads();
        if (slot == 1 && cch < NCHUNK) {
#pragma unroll
            for (int jj = 0; jj < 8; jj++) sout[cch * 8 + jj] += acc[jj];
        }
        __syncthreads();
    } else {
        // ---------------- slow path (CAP < d <= MAXDEG+1; rare) ----------
        __syncthreads();
        if (t == 0) g_csr_cnt[i] = 0;
        float ds0 = 0.0f, ds1 = 0.0f;
        for (int e = w; e < d; e += 8) {
            int src = (e == deg) ? i : g_slots[i * MAXDEG + e];
            const float* asr = g_as + (size_t)src * HEADS;
            float v0 = asr[lane] + sad[lane];
            v0 = (v0 > 0.0f) ? v0 : NEG_SLOPE * v0;
            ds0 += __expf(v0);
            if (lane < HEADS - 32) {
                float v1 = asr[32 + lane] + sad[32 + lane];
                v1 = (v1 > 0.0f) ? v1 : NEG_SLOPE * v1;
                ds1 += __expf(v1);
            }
        }
        atomicAdd(&sden[lane], ds0);
        if (lane < HEADS - 32) atomicAdd(&sden[32 + lane], ds1);
        __syncthreads();
        if (t < HEADS) sden[t] = 1.0f / sden[t];
        __syncthreads();

        float2 acc0 = {0.f, 0.f}, acc1 = {0.f, 0.f};
        int q0 = t, q1 = t + 256;           // float-pair indices (< 400)
        int h0 = q0 >> 3, h1 = q1 >> 3;
        for (int e = 0; e < d; e++) {
            int src = (e == deg) ? i : g_slots[i * MAXDEG + e];
            const float2* r = (const float2*)(g_xpf + (size_t)src * HC);
            const float* asr = g_as + (size_t)src * HEADS;
            {
                float v = asr[h0] + sad[h0];
                v = (v > 0.0f) ? v : NEG_SLOPE * v;
                float a = __expf(v);
                float2 f = r[q0];
                acc0.x += a * f.x; acc0.y += a * f.y;
            }
            if (q1 < HC / 2) {
                float v = asr[h1] + sad[h1];
                v = (v > 0.0f) ? v : NEG_SLOPE * v;
                float a = __expf(v);
                float2 f = r[q1];
                acc1.x += a * f.x; acc1.y += a * f.y;
            }
        }
        ((float2*)sout)[q0] = acc0;
        if (q1 < HC / 2) ((float2*)sout)[q1] = acc1;
        __syncthreads();
    }

    // epilogue: parallel per-head normalize + head-mean, then pooled RED
    {
        int c = t & 15;          // channel
        int hg = t >> 4;         // head group 0..15
        float s = 0.f;
        for (int h = hg; h < HEADS; h += 16)
            s += sout[h * HID + c] * sden[h];
        sred[hg][c] = s;
    }
    __syncthreads();
    if (t < HID) {
        float s = 0.f;
#pragma unroll
        for (int g2 = 0; g2 < 16; g2++) s += sred[g2][t];
        atomicAdd(&g_gsum[batch[i] * HID + t], s * (1.0f / (float)HEADS));
    }
    if (t == 0) atomicAdd(&g_gcnt[batch[i]], 1.0f);

    // ---- last-block ticket: final FC fused here (no separate launch) ----
    __threadfence();
    __syncthreads();
    if (t == 0) slast = (atomicAdd(&g_done, 1) == gridDim.x - 1) ? 1 : 0;
    __syncthreads();
    if (slast) {
        // all other blocks' REDs are visible (they fenced before ticket)
        if (t < N_GRAPHS * OUT_DIM) {
            int g = t / OUT_DIM, o = t - g * OUT_DIM;
            float inv = 1.0f / fmaxf(__ldcg(&g_gcnt[g]), 1.0f);
            float s = fc_b[o];
#pragma unroll
            for (int c = 0; c < HID; c++)
                s += (__ldcg(&g_gsum[g * HID + c]) * inv + bias[c]) * fc_w[c * OUT_DIM + o];
            out[t] = s;
        }
        __syncthreads();
        // restore zero-invariants for the next graph replay
        if (t < N_GRAPHS * HID) g_gsum[t] = 0.0f;
        if (t < N_GRAPHS) g_gcnt[t] = 0.0f;
        if (t == 0) g_done = 0;
    }
}

extern "C" void kernel_launch(void* const* d_in, const int* in_sizes, int n_in,
                              void* d_out, int out_size) {
    const float* x = nullptr;
    const int* ei = nullptr;       // int32 (JAX x64 disabled)
    const int* batch = nullptr;
    const float* W = nullptr;
    const float* a_src = nullptr;
    const float* a_dst = nullptr;
    const float* bias = nullptr;
    const float* fc_w = nullptr;
    const float* fc_b = nullptr;

    for (int i = 0; i < n_in; i++) {
        int s = in_sizes[i];
        switch (s) {
            case N_NODES * IN_DIM:  x = (const float*)d_in[i]; break;
            case 2 * N_EDGES:       ei = (const int*)d_in[i]; break;
            case N_NODES:           batch = (const int*)d_in[i]; break;
            case IN_DIM * HC:       W = (const float*)d_in[i]; break;
            case HEADS * HID:
                if (!a_src) a_src = (const float*)d_in[i];
                else a_dst = (const float*)d_in[i];
                break;
            case HID:               bias = (const float*)d_in[i]; break;
            case HID * OUT_DIM:     fc_w = (const float*)d_in[i]; break;
            case OUT_DIM:           fc_b = (const float*)d_in[i]; break;
            default: break;
        }
    }
    float* out = (float*)d_out;

    k_fillgemm<<<GEMM_BLOCKS + FILL_BLOCKS, 256>>>(x, W, ei);
    k_alphas<<<(N_NODES * HEADS + 255) / 256, 256>>>(a_src, a_dst);
    k_agg<<<N_NODES, 256>>>(batch, bias, fc_w, fc_b, out);
}

// round 16
// speedup vs baseline: 1.2834x; 1.2834x over previous
#include <cuda_runtime.h>
#include <cuda_bf16.h>
#include <math.h>
#include <stdint.h>

// Problem constants
#define N_NODES   10000
#define N_EDGES   160000
#define IN_DIM    128
#define HID       16
#define HEADS     50
#define HC        800           // HEADS*HID
#define OUT_DIM   10
#define N_GRAPHS  8
#define NEG_SLOPE 0.2f
#define MAXDEG    96
#define LOG2E     1.4426950408889634f

// Scratch (device globals; zero-initialized at load)
__device__ __nv_bfloat16 g_xpb[N_NODES * HC];   // 16 MB bf16 projected features
__device__ float g_as[N_NODES * HEADS];         // prescaled by log2e
__device__ float g_ad[N_NODES * HEADS];         // prescaled by log2e
__device__ float g_gsum[N_GRAPHS * HID];
__device__ float g_gcnt[N_GRAPHS];
// direct-slot adjacency (by destination)
__device__ int g_csr_cnt[N_NODES];   // invariant: zero at start of every run
__device__ int g_slots[N_NODES * MAXDEG];

__device__ __forceinline__ float ex2f(float x) {
    float r;
    asm("ex2.approx.f32 %0, %1;" : "=f"(r) : "f"(x));
    return r;
}

// ---------------- tf32 GEMM (+ fused adjacency fill blocks) ---------------
#define GBM 128
#define GBN 64
#define GBK 32
#define ASTR 36
#define BSTR 68
#define NKT  (IN_DIM / GBK)
#define GEMM_BX ((HC + GBN - 1) / GBN)        // 13
#define GEMM_BY ((N_NODES + GBM - 1) / GBM)   // 79
#define GEMM_BLOCKS (GEMM_BX * GEMM_BY)       // 1027
#define FILL_BLOCKS ((N_EDGES + 255) / 256)   // 625

__device__ __forceinline__ void cp16(uint32_t dst, const float* src, int pred_bytes) {
    asm volatile("cp.async.ca.shared.global [%0], [%1], 16, %2;"
                 :: "r"(dst), "l"(src), "r"(pred_bytes));
}

__device__ __forceinline__ uint32_t f2tf32(float f) {
    uint32_t r;
    asm("cvt.rna.tf32.f32 %0, %1;" : "=r"(r) : "f"(f));
    return r;
}

__device__ __forceinline__ void mma_tf32(float c[4], const uint32_t a[4], const uint32_t b[2]) {
    asm volatile(
        "mma.sync.aligned.m16n8k8.row.col.f32.tf32.tf32.f32 "
        "{%0,%1,%2,%3}, {%4,%5,%6,%7}, {%8,%9}, {%0,%1,%2,%3};"
        : "+f"(c[0]), "+f"(c[1]), "+f"(c[2]), "+f"(c[3])
        : "r"(a[0]), "r"(a[1]), "r"(a[2]), "r"(a[3]), "r"(b[0]), "r"(b[1]));
}

__global__ void __launch_bounds__(256) k_fillgemm(const float* __restrict__ A,
                                                  const float* __restrict__ B,
                                                  const int* __restrict__ ei) {
    __shared__ float As[2][GBM][ASTR];
    __shared__ float Bs[2][GBK][BSTR];

    if (blockIdx.x >= GEMM_BLOCKS) {
        // adjacency fill (direct slots; no count/scan passes)
        int i = (blockIdx.x - GEMM_BLOCKS) * 256 + threadIdx.x;
        if (i < N_EDGES) {
            int dst = ei[N_EDGES + i];
            int k = atomicAdd(&g_csr_cnt[dst], 1);
            if (k < MAXDEG) g_slots[dst * MAXDEG + k] = ei[i];
        }
        return;
    }

    int tid = threadIdx.x;
    int lane = tid & 31;
    int warp = tid >> 5;
    int wm = warp >> 1;
    int wn = warp & 1;
    int grp = lane >> 2;
    int thr = lane & 3;
    int rowBase = (blockIdx.x / GEMM_BX) * GBM;
    int colBase = (blockIdx.x % GEMM_BX) * GBN;

    uint32_t sA0 = (uint32_t)__cvta_generic_to_shared(&As[0][0][0]);
    uint32_t sB0 = (uint32_t)__cvta_generic_to_shared(&Bs[0][0][0]);
    const uint32_t sAstage = GBM * ASTR * 4;
    const uint32_t sBstage = GBK * BSTR * 4;

    int ar[4], ac4[4], apred[4];
#pragma unroll
    for (int i = 0; i < 4; i++) {
        int idx = i * 256 + tid;
        ar[i] = idx >> 3;
        ac4[i] = idx & 7;
        apred[i] = (rowBase + ar[i] < N_NODES) ? 16 : 0;
    }
    int br[2], bc4[2], bpred[2];
#pragma unroll
    for (int i = 0; i < 2; i++) {
        int idx = i * 256 + tid;
        br[i] = idx >> 4;
        bc4[i] = idx & 15;
        bpred[i] = (colBase + bc4[i] * 4 < HC) ? 16 : 0;
    }

#pragma unroll
    for (int i = 0; i < 4; i++)
        cp16(sA0 + (ar[i] * ASTR + ac4[i] * 4) * 4,
             A + (size_t)(rowBase + ar[i]) * IN_DIM + ac4[i] * 4, apred[i]);
#pragma unroll
    for (int i = 0; i < 2; i++)
        cp16(sB0 + (br[i] * BSTR + bc4[i] * 4) * 4,
             B + (size_t)br[i] * HC + colBase + bc4[i] * 4, bpred[i]);
    asm volatile("cp.async.commit_group;");

    float c[2][4][4];
#pragma unroll
    for (int mt = 0; mt < 2; mt++)
#pragma unroll
        for (int nt = 0; nt < 4; nt++)
#pragma unroll
            for (int r = 0; r < 4; r++) c[mt][nt][r] = 0.0f;

#pragma unroll
    for (int kt = 0; kt < NKT; kt++) {
        int buf = kt & 1;
        if (kt + 1 < NKT) {
            int k0 = (kt + 1) * GBK;
            uint32_t dA = sA0 + (buf ^ 1) * sAstage;
            uint32_t dB = sB0 + (buf ^ 1) * sBstage;
#pragma unroll
            for (int i = 0; i < 4; i++)
                cp16(dA + (ar[i] * ASTR + ac4[i] * 4) * 4,
                     A + (size_t)(rowBase + ar[i]) * IN_DIM + k0 + ac4[i] * 4, apred[i]);
#pragma unroll
            for (int i = 0; i < 2; i++)
                cp16(dB + (br[i] * BSTR + bc4[i] * 4) * 4,
                     B + (size_t)(k0 + br[i]) * HC + colBase + bc4[i] * 4, bpred[i]);
            asm volatile("cp.async.commit_group;");
            asm volatile("cp.async.wait_group 1;");
        } else {
            asm volatile("cp.async.wait_group 0;");
        }
        __syncthreads();

        const float (*Ab)[ASTR] = As[buf];
        const float (*Bb)[BSTR] = Bs[buf];
#pragma unroll
        for (int kk = 0; kk < GBK; kk += 8) {
            uint32_t af[2][4], bf[4][2];
#pragma unroll
            for (int mt = 0; mt < 2; mt++) {
                int rb = wm * 32 + mt * 16;
                af[mt][0] = f2tf32(Ab[rb + grp][kk + thr]);
                af[mt][1] = f2tf32(Ab[rb + grp + 8][kk + thr]);
                af[mt][2] = f2tf32(Ab[rb + grp][kk + thr + 4]);
                af[mt][3] = f2tf32(Ab[rb + grp + 8][kk + thr + 4]);
            }
#pragma unroll
            for (int nt = 0; nt < 4; nt++) {
                int cb = wn * 32 + nt * 8;
                bf[nt][0] = f2tf32(Bb[kk + thr][cb + grp]);
                bf[nt][1] = f2tf32(Bb[kk + thr + 4][cb + grp]);
            }
#pragma unroll
            for (int mt = 0; mt < 2; mt++)
#pragma unroll
                for (int nt = 0; nt < 4; nt++)
                    mma_tf32(c[mt][nt], af[mt], bf[nt]);
        }
        __syncthreads();
    }

#pragma unroll
    for (int mt = 0; mt < 2; mt++) {
#pragma unroll
        for (int nt = 0; nt < 4; nt++) {
            int row0 = rowBase + wm * 32 + mt * 16 + grp;
            int col = colBase + wn * 32 + nt * 8 + thr * 2;
            if (col + 1 < HC) {
                if (row0 < N_NODES) {
                    __nv_bfloat162 p = __floats2bfloat162_rn(c[mt][nt][0], c[mt][nt][1]);
                    *(__nv_bfloat162*)&g_xpb[(size_t)row0 * HC + col] = p;
                }
                if (row0 + 8 < N_NODES) {
                    __nv_bfloat162 p = __floats2bfloat162_rn(c[mt][nt][2], c[mt][nt][3]);
                    *(__nv_bfloat162*)&g_xpb[(size_t)(row0 + 8) * HC + col] = p;
                }
            }
        }
    }
}

// ---------------- per-(node,head) attention dots from bf16 xp -------------
// outputs prescaled by log2e so k_agg can use raw ex2.
__global__ void __launch_bounds__(256) k_alphas(const float* __restrict__ a_src,
                                                const float* __restrict__ a_dst) {
    __shared__ float sas[HC];
    __shared__ float sad[HC];
    int t = threadIdx.x;
    for (int j = t; j < HC; j += 256) {
        sas[j] = a_src[j];
        sad[j] = a_dst[j];
    }
    __syncthreads();
    int i = blockIdx.x * 256 + t;
    if (i >= N_NODES * HEADS) return;
    int h = i % HEADS;
    const __nv_bfloat16* xr = g_xpb + (size_t)(i / HEADS) * HC + h * HID;
    uint4 u0 = ((const uint4*)xr)[0];
    uint4 u1 = ((const uint4*)xr)[1];
    uint32_t w[8] = {u0.x, u0.y, u0.z, u0.w, u1.x, u1.y, u1.z, u1.w};
    float s = 0.0f, d = 0.0f;
    const float* as = sas + h * HID;
    const float* ad = sad + h * HID;
#pragma unroll
    for (int j = 0; j < 8; j++) {
        __nv_bfloat162 b = *(__nv_bfloat162*)&w[j];
        float x0 = __bfloat162float(b.x);
        float x1 = __bfloat162float(b.y);
        s += x0 * as[2 * j] + x1 * as[2 * j + 1];
        d += x0 * ad[2 * j] + x1 * ad[2 * j + 1];
    }
    g_as[i] = s * LOG2E;
    g_ad[i] = d * LOG2E;
}

// ---------------- fused softmax + aggregate + pool (block per node) -------
#define CAP 64
#define NCHUNK (HC / 8)      // 100 uint4 chunks per row

__global__ void __launch_bounds__(256, 7) k_agg(const int* __restrict__ batch) {
    __shared__ float salpha[CAP * HEADS];   // 12.8 KB (raw 2^x weights)
    __shared__ float sout[HC];              // 3.2 KB
    __shared__ float sred[16][17];          // 1.1 KB epilogue tree
    __shared__ int      ssrc[CAP];          // src node ids (phase A)
    __shared__ uint32_t sbase[CAP];         // xpb byte offsets (phase B)
    __shared__ float sad[HEADS];
    __shared__ float sden[HEADS];

    int i = blockIdx.x;
    int t = threadIdx.x;
    int w = t >> 5, lane = t & 31;
    int deg = g_csr_cnt[i];                 // read by EVERY thread (pre-reset)
    if (deg > MAXDEG) deg = MAXDEG;
    int d = deg + 1;                        // + self loop at index deg

    if (t < HEADS) {
        sad[t] = g_ad[i * HEADS + t];
        sden[t] = 0.0f;
    }

    if (d <= CAP) {
        // ---------------- fast path ----------------
        if (t < d) {
            int s = (t < deg) ? g_slots[i * MAXDEG + t] : i;
            ssrc[t] = s;
            sbase[t] = (uint32_t)s * (HC * 2);   // byte offset into g_xpb
        }
        __syncthreads();
        // reset AFTER the barrier: every thread's deg read is ordered before this store
        if (t == 0) g_csr_cnt[i] = 0;

        // phase A: warp per edge, lane = head; register-hoisted sad, raw ex2
        float sadl0 = sad[lane];
        float sadl1 = (lane < HEADS - 32) ? sad[32 + lane] : 0.0f;
        float ds0 = 0.0f, ds1 = 0.0f;
        for (int e = w; e < d; e += 8) {
            const float* asr = g_as + (size_t)ssrc[e] * HEADS;
            float v0 = asr[lane] + sadl0;
            v0 = (v0 > 0.0f) ? v0 : NEG_SLOPE * v0;
            float ex0 = ex2f(v0);
            salpha[e * HEADS + lane] = ex0;
            ds0 += ex0;
            if (lane < HEADS - 32) {
                float v1 = asr[32 + lane] + sadl1;
                v1 = (v1 > 0.0f) ? v1 : NEG_SLOPE * v1;
                float ex1 = ex2f(v1);
                salpha[e * HEADS + 32 + lane] = ex1;
                ds1 += ex1;
            }
        }
        atomicAdd(&sden[lane], ds0);
        if (lane < HEADS - 32) atomicAdd(&sden[32 + lane], ds1);
        __syncthreads();
        if (t < HEADS) sden[t] = 1.0f / sden[t];

        // phase B: strided loop unrolled x3 (three independent LDGs in flight)
        int slot = t >> 7;            // 0 or 1
        int cch = t & 127;            // chunk id, active if < NCHUNK
        float acc[8] = {0.f, 0.f, 0.f, 0.f, 0.f, 0.f, 0.f, 0.f};
        if (cch < NCHUNK) {
            int hsel = cch >> 1;
            const char* xb = (const char*)g_xpb;
            uint32_t coff = cch * 16;
            int e = slot;
            for (; e + 4 < d; e += 6) {
                uint4 ua = *(const uint4*)(xb + sbase[e] + coff);
                uint4 ub = *(const uint4*)(xb + sbase[e + 2] + coff);
                uint4 uc = *(const uint4*)(xb + sbase[e + 4] + coff);
                float wa = salpha[e * HEADS + hsel];
                float wb = salpha[(e + 2) * HEADS + hsel];
                float wc = salpha[(e + 4) * HEADS + hsel];
                uint32_t wsa[4] = {ua.x, ua.y, ua.z, ua.w};
                uint32_t wsb[4] = {ub.x, ub.y, ub.z, ub.w};
                uint32_t wsc[4] = {uc.x, uc.y, uc.z, uc.w};
#pragma unroll
                for (int jj = 0; jj < 4; jj++) {
                    float2 f = __bfloat1622float2(*(__nv_bfloat162*)&wsa[jj]);
                    acc[2 * jj]     += wa * f.x;
                    acc[2 * jj + 1] += wa * f.y;
                }
#pragma unroll
                for (int jj = 0; jj < 4; jj++) {
                    float2 f = __bfloat1622float2(*(__nv_bfloat162*)&wsb[jj]);
                    acc[2 * jj]     += wb * f.x;
                    acc[2 * jj + 1] += wb * f.y;
                }
#pragma unroll
                for (int jj = 0; jj < 4; jj++) {
                    float2 f = __bfloat1622float2(*(__nv_bfloat162*)&wsc[jj]);
                    acc[2 * jj]     += wc * f.x;
                    acc[2 * jj + 1] += wc * f.y;
                }
            }
            for (; e < d; e += 2) {
                uint4 u = *(const uint4*)(xb + sbase[e] + coff);
                float wgt = salpha[e * HEADS + hsel];
                uint32_t ws[4] = {u.x, u.y, u.z, u.w};
#pragma unroll
                for (int jj = 0; jj < 4; jj++) {
                    float2 f = __bfloat1622float2(*(__nv_bfloat162*)&ws[jj]);
                    acc[2 * jj]     += wgt * f.x;
                    acc[2 * jj + 1] += wgt * f.y;
                }
            }
        }
        if (slot == 0 && cch < NCHUNK) {
#pragma unroll
            for (int jj = 0; jj < 8; jj++) sout[cch * 8 + jj] = acc[jj];
        }
        __syncthreads();
        if (slot == 1 && cch < NCHUNK) {
#pragma unroll
            for (int jj = 0; jj < 8; jj++) sout[cch * 8 + jj] += acc[jj];
        }
        __syncthreads();
    } else {
        // ---------------- slow path (CAP < d <= MAXDEG+1; rare) ----------
        __syncthreads();
        if (t == 0) g_csr_cnt[i] = 0;
        float sadl0 = sad[lane];
        float sadl1 = (lane < HEADS - 32) ? sad[32 + lane] : 0.0f;
        float ds0 = 0.0f, ds1 = 0.0f;
        for (int e = w; e < d; e += 8) {
            int src = (e == deg) ? i : g_slots[i * MAXDEG + e];
            const float* asr = g_as + (size_t)src * HEADS;
            float v0 = asr[lane] + sadl0;
            v0 = (v0 > 0.0f) ? v0 : NEG_SLOPE * v0;
            ds0 += ex2f(v0);
            if (lane < HEADS - 32) {
                float v1 = asr[32 + lane] + sadl1;
                v1 = (v1 > 0.0f) ? v1 : NEG_SLOPE * v1;
                ds1 += ex2f(v1);
            }
        }
        atomicAdd(&sden[lane], ds0);
        if (lane < HEADS - 32) atomicAdd(&sden[32 + lane], ds1);
        __syncthreads();
        if (t < HEADS) sden[t] = 1.0f / sden[t];
        __syncthreads();

        float2 acc0 = {0.f, 0.f}, acc1 = {0.f, 0.f};
        int q0 = t, q1 = t + 256;
        int h0 = q0 >> 3, h1 = q1 >> 3;
        for (int e = 0; e < d; e++) {
            int src = (e == deg) ? i : g_slots[i * MAXDEG + e];
            const __nv_bfloat162* r = (const __nv_bfloat162*)(g_xpb + (size_t)src * HC);
            const float* asr = g_as + (size_t)src * HEADS;
            {
                float v = asr[h0] + sad[h0];
                v = (v > 0.0f) ? v : NEG_SLOPE * v;
                float a = ex2f(v);
                float2 f = __bfloat1622float2(r[q0]);
                acc0.x += a * f.x; acc0.y += a * f.y;
            }
            if (q1 < HC / 2) {
                float v = asr[h1] + sad[h1];
                v = (v > 0.0f) ? v : NEG_SLOPE * v;
                float a = ex2f(v);
                float2 f = __bfloat1622float2(r[q1]);
                acc1.x += a * f.x; acc1.y += a * f.y;
            }
        }
        ((float2*)sout)[q0] = acc0;
        if (q1 < HC / 2) ((float2*)sout)[q1] = acc1;
        __syncthreads();
    }

    // epilogue: parallel per-head normalize + head-mean, then pooled RED
    {
        int c = t & 15;          // channel
        int hg = t >> 4;         // head group 0..15
        float s = 0.f;
        for (int h = hg; h < HEADS; h += 16)
            s += sout[h * HID + c] * sden[h];
        sred[hg][c] = s;
    }
    __syncthreads();
    if (t < HID) {
        float s = 0.f;
#pragma unroll
        for (int g2 = 0; g2 < 16; g2++) s += sred[g2][t];
        atomicAdd(&g_gsum[batch[i] * HID + t], s * (1.0f / (float)HEADS));
    }
    if (t == 0) atomicAdd(&g_gcnt[batch[i]], 1.0f);
}

// ---------------- final FC (applies /cnt, +bias; then re-zeros pools) -----
__global__ void k_fc(const float* __restrict__ bias,
                     const float* __restrict__ fc_w, const float* __restrict__ fc_b,
                     float* __restrict__ out) {
    int i = threadIdx.x;
    if (i < N_GRAPHS * OUT_DIM) {
        int g = i / OUT_DIM, o = i - g * OUT_DIM;
        float inv = 1.0f / fmaxf(g_gcnt[g], 1.0f);
        float s = fc_b[o];
#pragma unroll
        for (int c = 0; c < HID; c++)
            s += (g_gsum[g * HID + c] * inv + bias[c]) * fc_w[c * OUT_DIM + o];
        out[i] = s;
    }
    __syncthreads();
    if (i < N_GRAPHS * HID) g_gsum[i] = 0.0f;   // restore zero-invariant
    if (i < N_GRAPHS) g_gcnt[i] = 0.0f;
}

extern "C" void kernel_launch(void* const* d_in, const int* in_sizes, int n_in,
                              void* d_out, int out_size) {
    const float* x = nullptr;
    const int* ei = nullptr;       // int32 (JAX x64 disabled)
    const int* batch = nullptr;
    const float* W = nullptr;
    const float* a_src = nullptr;
    const float* a_dst = nullptr;
    const float* bias = nullptr;
    const float* fc_w = nullptr;
    const float* fc_b = nullptr;

    for (int i = 0; i < n_in; i++) {
        int s = in_sizes[i];
        switch (s) {
            case N_NODES * IN_DIM:  x = (const float*)d_in[i]; break;
            case 2 * N_EDGES:       ei = (const int*)d_in[i]; break;
            case N_NODES:           batch = (const int*)d_in[i]; break;
            case IN_DIM * HC:       W = (const float*)d_in[i]; break;
            case HEADS * HID:
                if (!a_src) a_src = (const float*)d_in[i];
                else a_dst = (const float*)d_in[i];
                break;
            case HID:               bias = (const float*)d_in[i]; break;
            case HID * OUT_DIM:     fc_w = (const float*)d_in[i]; break;
            case OUT_DIM:           fc_b = (const float*)d_in[i]; break;
            default: break;
        }
    }
    float* out = (float*)d_out;

    k_fillgemm<<<GEMM_BLOCKS + FILL_BLOCKS, 256>>>(x, W, ei);
    k_alphas<<<(N_NODES * HEADS + 255) / 256, 256>>>(a_src, a_dst);
    k_agg<<<N_NODES, 256>>>(batch);
    k_fc<<<1, 160>>>(bias, fc_w, fc_b, out);
}